// round 6
// baseline (speedup 1.0000x reference)
#include <cuda_runtime.h>
#include <cstdint>

// B=32, S=2048, F=512. Output == per-row one-hot of argmax(logits+gumbel)
// (straight-through mask is exactly one-hot in fp32; the top-K zeroing only
// touches already-exact-zero entries — see R1 analysis).
//
// R5 == R4 resubmit (R4 bench died to a container-infra failure, never ran).
// 2 rows per warp, all 16 LDG.128 front-batched, to raise per-SM
// outstanding-miss count during reduce/store tails. Row pairing is
// (warp, warp + ROWS/2) to keep each block's traffic in two dense streams.

static constexpr int F_DIM     = 512;
static constexpr int F4        = F_DIM / 4;      // 128 float4 per row
static constexpr int ROWS      = 32 * 2048;      // 65536
static constexpr int HALF      = ROWS / 2;       // 32768
static constexpr int WARPS_B   = 16;
static constexpr int THREADS   = WARPS_B * 32;   // 512
static constexpr int BLOCKS    = HALF / WARPS_B; // 2048

__global__ __launch_bounds__(THREADS)
void onehot_argmax_kernel(const float4* __restrict__ logits,
                          const float4* __restrict__ gumbel,
                          float4* __restrict__ out) {
    const int warp = blockIdx.x * WARPS_B + (threadIdx.x >> 5);
    const int lane = threadIdx.x & 31;
    const size_t base0 = (size_t)warp * F4;
    const size_t base1 = base0 + (size_t)HALF * F4;

    float s0[16], s1[16];

    // 16 coalesced LDG.128 per lane, front-batched (MLP=16 per warp).
    #pragma unroll
    for (int it = 0; it < 4; it++) {
        const int off = it * 32 + lane;
        const float4 a0 = logits[base0 + off];
        const float4 g0 = gumbel[base0 + off];
        const float4 a1 = logits[base1 + off];
        const float4 g1 = gumbel[base1 + off];
        s0[it*4+0] = a0.x + g0.x;  s0[it*4+1] = a0.y + g0.y;
        s0[it*4+2] = a0.z + g0.z;  s0[it*4+3] = a0.w + g0.w;
        s1[it*4+0] = a1.x + g1.x;  s1[it*4+1] = a1.y + g1.y;
        s1[it*4+2] = a1.z + g1.z;  s1[it*4+3] = a1.w + g1.w;
    }

    // Two independent value-max reductions (ILP in fmax + shfl chains).
    float v0 = s0[0], v1 = s1[0];
    #pragma unroll
    for (int i = 1; i < 16; i++) { v0 = fmaxf(v0, s0[i]); v1 = fmaxf(v1, s1[i]); }
    #pragma unroll
    for (int o = 16; o > 0; o >>= 1) {
        v0 = fmaxf(v0, __shfl_xor_sync(0xFFFFFFFFu, v0, o));
        v1 = fmaxf(v1, __shfl_xor_sync(0xFFFFFFFFu, v1, o));
    }

    // First-occurrence index of the max (jnp tie-break): per-lane min
    // matching index, then one REDUX.min per row.
    unsigned c0 = 0xFFFFFFFFu, c1 = 0xFFFFFFFFu;
    #pragma unroll
    for (int it = 0; it < 4; it++) {
        const int e = (it * 32 + lane) * 4;
        #pragma unroll
        for (int c = 0; c < 4; c++) {
            if (s0[it*4+c] == v0) c0 = min(c0, (unsigned)(e + c));
            if (s1[it*4+c] == v1) c1 = min(c1, (unsigned)(e + c));
        }
    }
    const unsigned best0 = __reduce_min_sync(0xFFFFFFFFu, c0);
    const unsigned best1 = __reduce_min_sync(0xFFFFFFFFu, c1);

    // Coalesced one-hot stores (8 STG.128 per lane).
    #pragma unroll
    for (int it = 0; it < 4; it++) {
        const int off = it * 32 + lane;
        const unsigned e = (unsigned)(off * 4);
        float4 w0 = make_float4(0.f, 0.f, 0.f, 0.f);
        float4 w1 = make_float4(0.f, 0.f, 0.f, 0.f);
        const unsigned d0 = best0 - e;
        const unsigned d1 = best1 - e;
        if (d0 < 4u) (&w0.x)[d0] = 1.0f;
        if (d1 < 4u) (&w1.x)[d1] = 1.0f;
        out[base0 + off] = w0;
        out[base1 + off] = w1;
    }
}

extern "C" void kernel_launch(void* const* d_in, const int* in_sizes, int n_in,
                              void* d_out, int out_size) {
    const float4* logits = (const float4*)d_in[0];
    const float4* gumbel = (const float4*)d_in[1];
    float4* out = (float4*)d_out;

    onehot_argmax_kernel<<<BLOCKS, THREADS>>>(logits, gumbel, out);
}

// round 7
// speedup vs baseline: 1.0648x; 1.0648x over previous
#include <cuda_runtime.h>
#include <cstdint>

// B=32, S=2048, F=512. Output == per-row one-hot of argmax(logits+gumbel):
// the straight-through mask is exactly one-hot in fp32, and the reference's
// top-K(=104857) "zero the smallest" scatter only touches entries that are
// already exactly zero (1,046,528 exact zeros per batch >> K). So the whole
// problem reduces to a per-row argmax + one-hot write: a pure 402 MB stream.
//
// R6 == R3 revert (best measured: 52.96us kernel, 83.8% DRAM, 6.6 TB/s).
// R5's 2-rows/warp variant regressed (occ 59->42%, DRAM 84->74%): MLP_p1=16
// deepened cross-CTA L1tex-queue contention and starved the reduce/store
// tails of resident warps. MLP_p1=8 @ 512-thread blocks is the sweet spot;
// .cs streaming hints also measured worse (R2). Converged at the HBM ceiling.

static constexpr int F_DIM   = 512;
static constexpr int F4      = F_DIM / 4;        // 128 float4 per row
static constexpr int ROWS    = 32 * 2048;        // 65536
static constexpr int WARPS_B = 16;               // warps (rows) per block
static constexpr int THREADS = WARPS_B * 32;     // 512

__global__ __launch_bounds__(THREADS)
void onehot_argmax_kernel(const float4* __restrict__ logits,
                          const float4* __restrict__ gumbel,
                          float4* __restrict__ out) {
    const int warp = blockIdx.x * WARPS_B + (threadIdx.x >> 5);
    const int lane = threadIdx.x & 31;
    const size_t base = (size_t)warp * F4;

    float s[16];

    // Front-batched, fully coalesced loads (8 LDG.128 per lane, MLP_p1=8).
    #pragma unroll
    for (int it = 0; it < 4; it++) {
        const int off = it * 32 + lane;
        const float4 a = logits[base + off];
        const float4 g = gumbel[base + off];
        s[it * 4 + 0] = a.x + g.x;
        s[it * 4 + 1] = a.y + g.y;
        s[it * 4 + 2] = a.z + g.z;
        s[it * 4 + 3] = a.w + g.w;
    }

    // Value max: 15 fmaxf (fma pipe) + 5-step butterfly.
    float vmax = s[0];
    #pragma unroll
    for (int i = 1; i < 16; i++) vmax = fmaxf(vmax, s[i]);
    #pragma unroll
    for (int o = 16; o > 0; o >>= 1)
        vmax = fmaxf(vmax, __shfl_xor_sync(0xFFFFFFFFu, vmax, o));

    // Index of FIRST occurrence of vmax (jnp argmax tie-break):
    // per-lane min matching index, then one REDUX.min across the warp.
    unsigned cand = 0xFFFFFFFFu;
    #pragma unroll
    for (int it = 0; it < 4; it++) {
        const int e = (it * 32 + lane) * 4;
        #pragma unroll
        for (int c = 0; c < 4; c++) {
            if (s[it * 4 + c] == vmax) cand = min(cand, (unsigned)(e + c));
        }
    }
    const unsigned best = __reduce_min_sync(0xFFFFFFFFu, cand);

    // Coalesced one-hot stores (4 STG.128 per lane).
    #pragma unroll
    for (int it = 0; it < 4; it++) {
        const int off = it * 32 + lane;
        const unsigned e = (unsigned)(off * 4);
        float4 v = make_float4(0.f, 0.f, 0.f, 0.f);
        const unsigned d = best - e;
        if (d < 4u) (&v.x)[d] = 1.0f;
        out[base + off] = v;
    }
}

extern "C" void kernel_launch(void* const* d_in, const int* in_sizes, int n_in,
                              void* d_out, int out_size) {
    const float4* logits = (const float4*)d_in[0];
    const float4* gumbel = (const float4*)d_in[1];
    float4* out = (float4*)d_out;

    onehot_argmax_kernel<<<ROWS / WARPS_B, THREADS>>>(logits, gumbel, out);
}